// round 2
// baseline (speedup 1.0000x reference)
#include <cuda_runtime.h>
#include <cstdint>

#define NN 50000
#define EE 800000
#define ETOT (EE + NN)
#define DD 128
#define NBSCAN ((NN + 1023) / 1024)

// ---------------- static device scratch ----------------
__device__ float g_h[NN * DD];
__device__ float g_xl[NN * DD];
__device__ float g_xr[NN * DD];
__device__ int   g_deg[NN];
__device__ int   g_offs[NN + 1];
__device__ int   g_cur[NN];
__device__ int   g_srcs[ETOT];
__device__ int   g_bsums[NBSCAN];

// ---------------- CSR build ----------------
__global__ void zero_counts() {
    int i = blockIdx.x * blockDim.x + threadIdx.x;
    if (i < NN) { g_deg[i] = 0; g_cur[i] = 0; }
}

__global__ void count_edges(const int* __restrict__ ei) {
    int t = blockIdx.x * blockDim.x + threadIdx.x;
    if (t < ETOT) {
        int dst = (t < EE) ? ei[EE + t] : (t - EE);
        atomicAdd(&g_deg[dst], 1);
    }
}

__global__ void scan_block() {
    __shared__ int sm[256];
    int t = threadIdx.x;
    int base = blockIdx.x * 1024 + t * 4;
    int v0 = (base + 0 < NN) ? g_deg[base + 0] : 0;
    int v1 = (base + 1 < NN) ? g_deg[base + 1] : 0;
    int v2 = (base + 2 < NN) ? g_deg[base + 2] : 0;
    int v3 = (base + 3 < NN) ? g_deg[base + 3] : 0;
    v1 += v0; v2 += v1; v3 += v2;
    sm[t] = v3;
    __syncthreads();
    #pragma unroll
    for (int off = 1; off < 256; off <<= 1) {
        int add = (t >= off) ? sm[t - off] : 0;
        __syncthreads();
        sm[t] += add;
        __syncthreads();
    }
    int prev = (t > 0) ? sm[t - 1] : 0;
    if (base + 0 < NN) g_offs[base + 0] = prev + v0;
    if (base + 1 < NN) g_offs[base + 1] = prev + v1;
    if (base + 2 < NN) g_offs[base + 2] = prev + v2;
    if (base + 3 < NN) g_offs[base + 3] = prev + v3;
    if (t == 255) g_bsums[blockIdx.x] = sm[255];
}

__global__ void scan_spine() {
    if (threadIdx.x == 0) {
        int acc = 0;
        for (int i = 0; i < NBSCAN; i++) { int v = g_bsums[i]; g_bsums[i] = acc; acc += v; }
    }
}

__global__ void scan_fix() {
    int i = blockIdx.x * blockDim.x + threadIdx.x;
    if (i < NN) g_offs[i] = g_offs[i] - g_deg[i] + g_bsums[i >> 10];
    if (i == 0) g_offs[NN] = ETOT;
}

__global__ void fill_edges(const int* __restrict__ ei) {
    int t = blockIdx.x * blockDim.x + threadIdx.x;
    if (t < ETOT) {
        int src, dst;
        if (t < EE) { src = ei[t]; dst = ei[EE + t]; }
        else        { src = t - EE; dst = src; }
        int pos = g_offs[dst] + atomicAdd(&g_cur[dst], 1);
        g_srcs[pos] = src;
    }
}

// ---------------- layer 0 GEMM (K=7, trivial) ----------------
__global__ void gemm0(const float* __restrict__ x,
                      const float* __restrict__ Wl0, const float* __restrict__ Wr0,
                      const float* __restrict__ bl0, const float* __restrict__ br0) {
    int node = blockIdx.x;
    int j = threadIdx.x;
    __shared__ float xs[7];
    if (j < 7) xs[j] = x[node * 7 + j];
    __syncthreads();
    const float* W = (j < 128) ? Wl0 : Wr0;
    int c = j & 127;
    float acc = (j < 128) ? bl0[c] : br0[c];
    #pragma unroll
    for (int k = 0; k < 7; k++) acc += xs[k] * W[k * 128 + c];
    if (j < 128) g_xl[node * DD + c] = acc;
    else         g_xr[node * DD + c] = acc;
}

// ---------------- tensor-core GEMM (3xTF32): relu(h)[N,128] x [128,256] ----------------
// Block: 64 rows x 256 cols, 8 warps (2x4), warp tile 32x64 = 2 m-tiles x 8 n-tiles of m16n8k8.
// A/B split into tf32 hi/lo in SMEM; acc = Ah*Bl + Al*Bh + Ah*Bh (near-fp32 accuracy).
#define KC 16

__device__ __forceinline__ uint32_t f2tf32(float x) {
    uint32_t r;
    asm volatile("cvt.rna.tf32.f32 %0, %1;" : "=r"(r) : "f"(x));
    return r;
}

__device__ __forceinline__ void mma_tf32(float c[4], const uint32_t a[4], uint32_t b0, uint32_t b1) {
    asm volatile(
        "mma.sync.aligned.m16n8k8.row.col.f32.tf32.tf32.f32 "
        "{%0,%1,%2,%3}, {%4,%5,%6,%7}, {%8,%9}, {%0,%1,%2,%3};"
        : "+f"(c[0]), "+f"(c[1]), "+f"(c[2]), "+f"(c[3])
        : "r"(a[0]), "r"(a[1]), "r"(a[2]), "r"(a[3]), "r"(b0), "r"(b1));
}

__global__ __launch_bounds__(256, 1) void gemm_tc(const float* __restrict__ Wl_,
                                                  const float* __restrict__ Wr_,
                                                  const float* __restrict__ bl_,
                                                  const float* __restrict__ br_) {
    __shared__ uint32_t AsH[64][20], AsL[64][20];     // [row][k], pad 16->20
    __shared__ uint32_t BsH[KC][264], BsL[KC][264];   // [k][col], pad 256->264

    int tid  = threadIdx.x;
    int lane = tid & 31;
    int wid  = tid >> 5;
    int g    = lane >> 2;       // groupID 0..7
    int tig  = lane & 3;        // thread-in-group 0..3
    int wm   = wid >> 2;        // 0..1
    int wn   = wid & 3;         // 0..3
    int m_base = wm * 32;
    int n_base = wn * 64;
    int row0 = blockIdx.x * 64;

    float c[2][8][4];
    #pragma unroll
    for (int mi = 0; mi < 2; mi++)
        #pragma unroll
        for (int ni = 0; ni < 8; ni++)
            #pragma unroll
            for (int q = 0; q < 4; q++) c[mi][ni][q] = 0.f;

    for (int k0 = 0; k0 < 128; k0 += KC) {
        // --- stage A (relu fused, split hi/lo) ---
        {
            int r  = tid >> 2;
            int kq = (tid & 3) * 4;
            int row = row0 + r;
            float4 v = make_float4(0.f, 0.f, 0.f, 0.f);
            if (row < NN) v = *(const float4*)&g_h[row * DD + k0 + kq];
            float f[4] = {fmaxf(v.x, 0.f), fmaxf(v.y, 0.f), fmaxf(v.z, 0.f), fmaxf(v.w, 0.f)};
            #pragma unroll
            for (int j = 0; j < 4; j++) {
                uint32_t hi = f2tf32(f[j]);
                float lo = f[j] - __uint_as_float(hi);
                AsH[r][kq + j] = hi;
                AsL[r][kq + j] = f2tf32(lo);
            }
        }
        // --- stage B (Wl | Wr, split hi/lo) ---
        #pragma unroll
        for (int q = 0; q < 4; q++) {
            int idx = (q * 256 + tid) * 4;
            int k = idx >> 8;
            int cc = idx & 255;
            const float* src = (cc < 128) ? &Wl_[(k0 + k) * 128 + cc]
                                          : &Wr_[(k0 + k) * 128 + (cc - 128)];
            float4 v = *(const float4*)src;
            float f[4] = {v.x, v.y, v.z, v.w};
            #pragma unroll
            for (int j = 0; j < 4; j++) {
                uint32_t hi = f2tf32(f[j]);
                float lo = f[j] - __uint_as_float(hi);
                BsH[k][cc + j] = hi;
                BsL[k][cc + j] = f2tf32(lo);
            }
        }
        __syncthreads();

        #pragma unroll
        for (int ks = 0; ks < KC; ks += 8) {
            uint32_t aH[2][4], aL[2][4];
            #pragma unroll
            for (int mi = 0; mi < 2; mi++) {
                int r = m_base + mi * 16 + g;
                aH[mi][0] = AsH[r][ks + tig];     aL[mi][0] = AsL[r][ks + tig];
                aH[mi][1] = AsH[r + 8][ks + tig]; aL[mi][1] = AsL[r + 8][ks + tig];
                aH[mi][2] = AsH[r][ks + tig + 4];     aL[mi][2] = AsL[r][ks + tig + 4];
                aH[mi][3] = AsH[r + 8][ks + tig + 4]; aL[mi][3] = AsL[r + 8][ks + tig + 4];
            }
            #pragma unroll
            for (int ni = 0; ni < 8; ni++) {
                int cc = n_base + ni * 8 + g;
                uint32_t bH0 = BsH[ks + tig][cc],     bL0 = BsL[ks + tig][cc];
                uint32_t bH1 = BsH[ks + tig + 4][cc], bL1 = BsL[ks + tig + 4][cc];
                #pragma unroll
                for (int mi = 0; mi < 2; mi++) {
                    mma_tf32(c[mi][ni], aH[mi], bL0, bL1);   // hi*lo
                    mma_tf32(c[mi][ni], aL[mi], bH0, bH1);   // lo*hi
                    mma_tf32(c[mi][ni], aH[mi], bH0, bH1);   // hi*hi
                }
            }
        }
        __syncthreads();
    }

    // --- epilogue: bias + scatter to g_xl / g_xr ---
    #pragma unroll
    for (int ni = 0; ni < 8; ni++) {
        int cn = n_base + ni * 8 + tig * 2;
        float b0, b1;
        if (cn < 128) { b0 = bl_[cn]; b1 = bl_[cn + 1]; }
        else          { b0 = br_[cn - 128]; b1 = br_[cn - 128 + 1]; }
        float* dst = (cn < 128) ? g_xl : g_xr;
        int cl = (cn < 128) ? cn : (cn - 128);
        #pragma unroll
        for (int mi = 0; mi < 2; mi++) {
            int ra = row0 + m_base + mi * 16 + g;
            int rb = ra + 8;
            if (ra < NN) {
                float2 o = make_float2(c[mi][ni][0] + b0, c[mi][ni][1] + b1);
                *(float2*)&dst[ra * DD + cl] = o;
            }
            if (rb < NN) {
                float2 o = make_float2(c[mi][ni][2] + b0, c[mi][ni][3] + b1);
                *(float2*)&dst[rb * DD + cl] = o;
            }
        }
    }
}

// ---------------- attention + aggregation: warp per node, online softmax ----------------
__global__ void attn(const float* __restrict__ avec, const float* __restrict__ bvec,
                     float* __restrict__ outp) {
    const unsigned FULL = 0xffffffffu;
    int w = (blockIdx.x * blockDim.x + threadIdx.x) >> 5;
    if (w >= NN) return;
    int lane = threadIdx.x & 31;

    float4 xr4 = *(float4*)&g_xr[w * DD + lane * 4];
    float4 a4  = *(const float4*)&avec[lane * 4];

    int p = g_offs[w], end = g_offs[w + 1];
    float m = -1e30f, s = 0.f;
    float ax = 0.f, ay = 0.f, az = 0.f, aw = 0.f;

    int src = g_srcs[p];
    float4 xl4 = *(float4*)&g_xl[src * DD + lane * 4];

    while (p < end) {
        float4 cur = xl4;
        int pn = p + 1;
        if (pn < end) {
            int s2 = g_srcs[pn];
            xl4 = *(float4*)&g_xl[s2 * DD + lane * 4];
        }
        float vx = cur.x + xr4.x; vx = (vx > 0.f) ? vx : 0.2f * vx;
        float vy = cur.y + xr4.y; vy = (vy > 0.f) ? vy : 0.2f * vy;
        float vz = cur.z + xr4.z; vz = (vz > 0.f) ? vz : 0.2f * vz;
        float vw = cur.w + xr4.w; vw = (vw > 0.f) ? vw : 0.2f * vw;
        float d = vx * a4.x + vy * a4.y + vz * a4.z + vw * a4.w;
        d += __shfl_xor_sync(FULL, d, 16);
        d += __shfl_xor_sync(FULL, d, 8);
        d += __shfl_xor_sync(FULL, d, 4);
        d += __shfl_xor_sync(FULL, d, 2);
        d += __shfl_xor_sync(FULL, d, 1);

        float mn  = fmaxf(m, d);
        float sc  = __expf(m - mn);
        float wgt = __expf(d - mn);
        s  = s * sc + wgt;
        ax = ax * sc + wgt * cur.x;
        ay = ay * sc + wgt * cur.y;
        az = az * sc + wgt * cur.z;
        aw = aw * sc + wgt * cur.w;
        m = mn;
        p = pn;
    }

    float inv = 1.f / s;
    float4 b4 = *(const float4*)&bvec[lane * 4];
    float* o = outp ? outp : g_h;
    float4 r = make_float4(ax * inv + b4.x, ay * inv + b4.y,
                           az * inv + b4.z, aw * inv + b4.w);
    *(float4*)&o[w * DD + lane * 4] = r;
}

// ---------------- launch ----------------
extern "C" void kernel_launch(void* const* d_in, const int* in_sizes, int n_in,
                              void* d_out, int out_size) {
    const float* x    = (const float*)d_in[0];
    const int*   ei   = (const int*)d_in[1];
    const float* Wl0  = (const float*)d_in[2];
    const float* Wr0  = (const float*)d_in[3];
    const float* bl0  = (const float*)d_in[4];
    const float* br0  = (const float*)d_in[5];
    const float* Wl   = (const float*)d_in[6];
    const float* Wr   = (const float*)d_in[7];
    const float* bl   = (const float*)d_in[8];
    const float* br   = (const float*)d_in[9];
    const float* att  = (const float*)d_in[10];
    const float* bias = (const float*)d_in[11];
    float* out = (float*)d_out;

    zero_counts<<<(NN + 255) / 256, 256>>>();
    count_edges<<<(ETOT + 255) / 256, 256>>>(ei);
    scan_block<<<NBSCAN, 256>>>();
    scan_spine<<<1, 32>>>();
    scan_fix<<<(NN + 255) / 256, 256>>>();
    fill_edges<<<(ETOT + 255) / 256, 256>>>(ei);

    const int attn_blocks = (NN * 32 + 255) / 256;
    const int tc_blocks   = (NN + 63) / 64;

    gemm0<<<NN, 256>>>(x, Wl0, Wr0, bl0, br0);
    attn<<<attn_blocks, 256>>>(att, bias, nullptr);

    for (int t = 1; t < 5; t++) {
        gemm_tc<<<tc_blocks, 256>>>(Wl + (size_t)(t - 1) * 128 * 128,
                                    Wr + (size_t)(t - 1) * 128 * 128,
                                    bl + (size_t)(t - 1) * 128,
                                    br + (size_t)(t - 1) * 128);
        attn<<<attn_blocks, 256>>>(att + (size_t)t * 128, bias + (size_t)t * 128,
                                   (t == 4) ? out : nullptr);
    }
}

// round 3
// speedup vs baseline: 1.0906x; 1.0906x over previous
#include <cuda_runtime.h>
#include <cstdint>

#define NN 50000
#define EE 800000
#define ETOT (EE + NN)
#define DD 128
#define NBSCAN ((NN + 1023) / 1024)

// ---------------- static device scratch ----------------
__device__ float g_h[NN * DD];
__device__ float g_xl[NN * DD];
__device__ float g_xr[NN * DD];
__device__ int   g_deg[NN];
__device__ int   g_offs[NN + 1];
__device__ int   g_cur[NN];
__device__ int   g_srcs[ETOT];
__device__ int   g_bsums[NBSCAN];
// pre-split tf32 weights: [layer][k][col], col 0..255 = (Wl | Wr)
__device__ uint32_t g_WH[4 * 128 * 256];
__device__ uint32_t g_WL[4 * 128 * 256];

__device__ __forceinline__ uint32_t f2tf32(float x) {
    uint32_t r;
    asm volatile("cvt.rna.tf32.f32 %0, %1;" : "=r"(r) : "f"(x));
    return r;
}

// ---------------- CSR build ----------------
__global__ void zero_counts() {
    int i = blockIdx.x * blockDim.x + threadIdx.x;
    if (i < NN) { g_deg[i] = 0; g_cur[i] = 0; }
}

__global__ void count_edges(const int* __restrict__ ei) {
    int t = blockIdx.x * blockDim.x + threadIdx.x;
    if (t < ETOT) {
        int dst = (t < EE) ? ei[EE + t] : (t - EE);
        atomicAdd(&g_deg[dst], 1);
    }
}

__global__ void scan_block() {
    __shared__ int sm[256];
    int t = threadIdx.x;
    int base = blockIdx.x * 1024 + t * 4;
    int v0 = (base + 0 < NN) ? g_deg[base + 0] : 0;
    int v1 = (base + 1 < NN) ? g_deg[base + 1] : 0;
    int v2 = (base + 2 < NN) ? g_deg[base + 2] : 0;
    int v3 = (base + 3 < NN) ? g_deg[base + 3] : 0;
    v1 += v0; v2 += v1; v3 += v2;
    sm[t] = v3;
    __syncthreads();
    #pragma unroll
    for (int off = 1; off < 256; off <<= 1) {
        int add = (t >= off) ? sm[t - off] : 0;
        __syncthreads();
        sm[t] += add;
        __syncthreads();
    }
    int prev = (t > 0) ? sm[t - 1] : 0;
    if (base + 0 < NN) g_offs[base + 0] = prev + v0;
    if (base + 1 < NN) g_offs[base + 1] = prev + v1;
    if (base + 2 < NN) g_offs[base + 2] = prev + v2;
    if (base + 3 < NN) g_offs[base + 3] = prev + v3;
    if (t == 255) g_bsums[blockIdx.x] = sm[255];
}

__global__ void scan_spine() {
    if (threadIdx.x == 0) {
        int acc = 0;
        for (int i = 0; i < NBSCAN; i++) { int v = g_bsums[i]; g_bsums[i] = acc; acc += v; }
    }
}

__global__ void scan_fix() {
    int i = blockIdx.x * blockDim.x + threadIdx.x;
    if (i < NN) g_offs[i] = g_offs[i] - g_deg[i] + g_bsums[i >> 10];
    if (i == 0) g_offs[NN] = ETOT;
}

__global__ void fill_edges(const int* __restrict__ ei) {
    int t = blockIdx.x * blockDim.x + threadIdx.x;
    if (t < ETOT) {
        int src, dst;
        if (t < EE) { src = ei[t]; dst = ei[EE + t]; }
        else        { src = t - EE; dst = src; }
        int pos = g_offs[dst] + atomicAdd(&g_cur[dst], 1);
        g_srcs[pos] = src;
    }
}

// ---------------- weight pre-split (all 4 mid layers, once per launch) ----------------
__global__ void split_w(const float* __restrict__ Wl, const float* __restrict__ Wr) {
    int i = blockIdx.x * blockDim.x + threadIdx.x;
    if (i >= 4 * 128 * 256) return;
    int layer = i >> 15;
    int rem = i & 32767;
    int k = rem >> 8;
    int c = rem & 255;
    float v = (c < 128) ? Wl[layer * 16384 + k * 128 + c]
                        : Wr[layer * 16384 + k * 128 + (c - 128)];
    uint32_t hi = f2tf32(v);
    float lo = v - __uint_as_float(hi);
    g_WH[i] = hi;
    g_WL[i] = f2tf32(lo);
}

// ---------------- layer 0 GEMM (K=7, trivial) ----------------
__global__ void gemm0(const float* __restrict__ x,
                      const float* __restrict__ Wl0, const float* __restrict__ Wr0,
                      const float* __restrict__ bl0, const float* __restrict__ br0) {
    int node = blockIdx.x;
    int j = threadIdx.x;
    __shared__ float xs[7];
    if (j < 7) xs[j] = x[node * 7 + j];
    __syncthreads();
    const float* W = (j < 128) ? Wl0 : Wr0;
    int c = j & 127;
    float acc = (j < 128) ? bl0[c] : br0[c];
    #pragma unroll
    for (int k = 0; k < 7; k++) acc += xs[k] * W[k * 128 + c];
    if (j < 128) g_xl[node * DD + c] = acc;
    else         g_xr[node * DD + c] = acc;
}

// ---------------- tensor-core GEMM (3xTF32), pre-split weights ----------------
// Grid: (ceil(N/128), 2).  y=0 -> Wl half -> g_xl;  y=1 -> Wr half -> g_xr.
// Block tile 128x128, 8 warps (4x2), warp tile 32x64 = 2 m16 x 8 n8.
#define KC 16

__device__ __forceinline__ void mma_tf32(float c[4], const uint32_t a[4], uint32_t b0, uint32_t b1) {
    asm volatile(
        "mma.sync.aligned.m16n8k8.row.col.f32.tf32.tf32.f32 "
        "{%0,%1,%2,%3}, {%4,%5,%6,%7}, {%8,%9}, {%0,%1,%2,%3};"
        : "+f"(c[0]), "+f"(c[1]), "+f"(c[2]), "+f"(c[3])
        : "r"(a[0]), "r"(a[1]), "r"(a[2]), "r"(a[3]), "r"(b0), "r"(b1));
}

__global__ __launch_bounds__(256) void gemm_tc(int layer,
                                               const float* __restrict__ bl_,
                                               const float* __restrict__ br_) {
    __shared__ uint32_t AsH[128][20], AsL[128][20];   // [row][k], pad 16->20
    __shared__ uint32_t BsH[KC][132], BsL[KC][132];   // [k][col], pad 128->132

    int tid  = threadIdx.x;
    int lane = tid & 31;
    int wid  = tid >> 5;
    int g    = lane >> 2;
    int tig  = lane & 3;
    int wm   = wid >> 1;        // 0..3
    int wn   = wid & 1;         // 0..1
    int m_base = wm * 32;
    int n_base = wn * 64;
    int row0 = blockIdx.x * 128;
    int yhalf = blockIdx.y;     // 0=Wl, 1=Wr

    const uint32_t* WHbase = g_WH + layer * 32768 + yhalf * 128;
    const uint32_t* WLbase = g_WL + layer * 32768 + yhalf * 128;

    float c[2][8][4];
    #pragma unroll
    for (int mi = 0; mi < 2; mi++)
        #pragma unroll
        for (int ni = 0; ni < 8; ni++)
            #pragma unroll
            for (int q = 0; q < 4; q++) c[mi][ni][q] = 0.f;

    int ar  = tid >> 1;                 // A stage: row
    int akq = (tid & 1) * 8;            // A stage: k offset (8 wide)
    int bk  = tid >> 4;                 // B stage: k (0..15)
    int bc  = (tid & 15) * 8;           // B stage: col offset (8 wide)

    for (int k0 = 0; k0 < 128; k0 += KC) {
        // --- stage A: relu + hi/lo split (2048 elems) ---
        {
            int row = row0 + ar;
            float4 v0 = make_float4(0.f, 0.f, 0.f, 0.f);
            float4 v1 = make_float4(0.f, 0.f, 0.f, 0.f);
            if (row < NN) {
                v0 = *(const float4*)&g_h[row * DD + k0 + akq];
                v1 = *(const float4*)&g_h[row * DD + k0 + akq + 4];
            }
            float f[8] = {fmaxf(v0.x, 0.f), fmaxf(v0.y, 0.f), fmaxf(v0.z, 0.f), fmaxf(v0.w, 0.f),
                          fmaxf(v1.x, 0.f), fmaxf(v1.y, 0.f), fmaxf(v1.z, 0.f), fmaxf(v1.w, 0.f)};
            #pragma unroll
            for (int j = 0; j < 8; j++) {
                uint32_t hi = f2tf32(f[j]);
                float lo = f[j] - __uint_as_float(hi);
                AsH[ar][akq + j] = hi;
                AsL[ar][akq + j] = f2tf32(lo);
            }
        }
        // --- stage B: pure copy of pre-split weights (2048 elems x2) ---
        {
            const uint32_t* sH = WHbase + (k0 + bk) * 256 + bc;
            const uint32_t* sL = WLbase + (k0 + bk) * 256 + bc;
            *(uint4*)&BsH[bk][bc]     = *(const uint4*)&sH[0];
            *(uint4*)&BsH[bk][bc + 4] = *(const uint4*)&sH[4];
            *(uint4*)&BsL[bk][bc]     = *(const uint4*)&sL[0];
            *(uint4*)&BsL[bk][bc + 4] = *(const uint4*)&sL[4];
        }
        __syncthreads();

        #pragma unroll
        for (int ks = 0; ks < KC; ks += 8) {
            uint32_t aH[2][4], aL[2][4];
            #pragma unroll
            for (int mi = 0; mi < 2; mi++) {
                int r = m_base + mi * 16 + g;
                aH[mi][0] = AsH[r][ks + tig];         aL[mi][0] = AsL[r][ks + tig];
                aH[mi][1] = AsH[r + 8][ks + tig];     aL[mi][1] = AsL[r + 8][ks + tig];
                aH[mi][2] = AsH[r][ks + tig + 4];     aL[mi][2] = AsL[r][ks + tig + 4];
                aH[mi][3] = AsH[r + 8][ks + tig + 4]; aL[mi][3] = AsL[r + 8][ks + tig + 4];
            }
            #pragma unroll
            for (int ni = 0; ni < 8; ni++) {
                int cc = n_base + ni * 8 + g;
                uint32_t bH0 = BsH[ks + tig][cc],     bL0 = BsL[ks + tig][cc];
                uint32_t bH1 = BsH[ks + tig + 4][cc], bL1 = BsL[ks + tig + 4][cc];
                #pragma unroll
                for (int mi = 0; mi < 2; mi++) {
                    mma_tf32(c[mi][ni], aH[mi], bL0, bL1);
                    mma_tf32(c[mi][ni], aL[mi], bH0, bH1);
                    mma_tf32(c[mi][ni], aH[mi], bH0, bH1);
                }
            }
        }
        __syncthreads();
    }

    // --- epilogue ---
    const float* bias = yhalf ? br_ : bl_;
    float* dst = yhalf ? g_xr : g_xl;
    #pragma unroll
    for (int ni = 0; ni < 8; ni++) {
        int cn = n_base + ni * 8 + tig * 2;
        float b0 = bias[cn], b1 = bias[cn + 1];
        #pragma unroll
        for (int mi = 0; mi < 2; mi++) {
            int ra = row0 + m_base + mi * 16 + g;
            int rb = ra + 8;
            if (ra < NN)
                *(float2*)&dst[ra * DD + cn] = make_float2(c[mi][ni][0] + b0, c[mi][ni][1] + b1);
            if (rb < NN)
                *(float2*)&dst[rb * DD + cn] = make_float2(c[mi][ni][2] + b0, c[mi][ni][3] + b1);
        }
    }
}

// ---------------- attention + aggregation: warp per node, online softmax ----------------
__global__ void attn(const float* __restrict__ avec, const float* __restrict__ bvec,
                     float* __restrict__ outp) {
    const unsigned FULL = 0xffffffffu;
    int w = (blockIdx.x * blockDim.x + threadIdx.x) >> 5;
    if (w >= NN) return;
    int lane = threadIdx.x & 31;

    float4 xr4 = *(float4*)&g_xr[w * DD + lane * 4];
    float4 a4  = *(const float4*)&avec[lane * 4];

    int p = g_offs[w], end = g_offs[w + 1];
    float m = -1e30f, s = 0.f;
    float ax = 0.f, ay = 0.f, az = 0.f, aw = 0.f;

    int src = g_srcs[p];
    float4 xl4 = *(float4*)&g_xl[src * DD + lane * 4];

    while (p < end) {
        float4 cur = xl4;
        int pn = p + 1;
        if (pn < end) {
            int s2 = g_srcs[pn];
            xl4 = *(float4*)&g_xl[s2 * DD + lane * 4];
        }
        float vx = cur.x + xr4.x; vx = (vx > 0.f) ? vx : 0.2f * vx;
        float vy = cur.y + xr4.y; vy = (vy > 0.f) ? vy : 0.2f * vy;
        float vz = cur.z + xr4.z; vz = (vz > 0.f) ? vz : 0.2f * vz;
        float vw = cur.w + xr4.w; vw = (vw > 0.f) ? vw : 0.2f * vw;
        float d = vx * a4.x + vy * a4.y + vz * a4.z + vw * a4.w;
        d += __shfl_xor_sync(FULL, d, 16);
        d += __shfl_xor_sync(FULL, d, 8);
        d += __shfl_xor_sync(FULL, d, 4);
        d += __shfl_xor_sync(FULL, d, 2);
        d += __shfl_xor_sync(FULL, d, 1);

        float mn  = fmaxf(m, d);
        float sc  = __expf(m - mn);
        float wgt = __expf(d - mn);
        s  = s * sc + wgt;
        ax = ax * sc + wgt * cur.x;
        ay = ay * sc + wgt * cur.y;
        az = az * sc + wgt * cur.z;
        aw = aw * sc + wgt * cur.w;
        m = mn;
        p = pn;
    }

    float inv = 1.f / s;
    float4 b4 = *(const float4*)&bvec[lane * 4];
    float* o = outp ? outp : g_h;
    float4 r = make_float4(ax * inv + b4.x, ay * inv + b4.y,
                           az * inv + b4.z, aw * inv + b4.w);
    *(float4*)&o[w * DD + lane * 4] = r;
}

// ---------------- launch ----------------
extern "C" void kernel_launch(void* const* d_in, const int* in_sizes, int n_in,
                              void* d_out, int out_size) {
    const float* x    = (const float*)d_in[0];
    const int*   ei   = (const int*)d_in[1];
    const float* Wl0  = (const float*)d_in[2];
    const float* Wr0  = (const float*)d_in[3];
    const float* bl0  = (const float*)d_in[4];
    const float* br0  = (const float*)d_in[5];
    const float* Wl   = (const float*)d_in[6];
    const float* Wr   = (const float*)d_in[7];
    const float* bl   = (const float*)d_in[8];
    const float* br   = (const float*)d_in[9];
    const float* att  = (const float*)d_in[10];
    const float* bias = (const float*)d_in[11];
    float* out = (float*)d_out;

    zero_counts<<<(NN + 255) / 256, 256>>>();
    count_edges<<<(ETOT + 255) / 256, 256>>>(ei);
    scan_block<<<NBSCAN, 256>>>();
    scan_spine<<<1, 32>>>();
    scan_fix<<<(NN + 255) / 256, 256>>>();
    fill_edges<<<(ETOT + 255) / 256, 256>>>(ei);
    split_w<<<(4 * 128 * 256 + 255) / 256, 256>>>(Wl, Wr);

    const int attn_blocks = (NN * 32 + 255) / 256;
    dim3 tc_grid((NN + 127) / 128, 2);

    gemm0<<<NN, 256>>>(x, Wl0, Wr0, bl0, br0);
    attn<<<attn_blocks, 256>>>(att, bias, nullptr);

    for (int t = 1; t < 5; t++) {
        gemm_tc<<<tc_grid, 256>>>(t - 1, bl + (size_t)(t - 1) * 128,
                                  br + (size_t)(t - 1) * 128);
        attn<<<attn_blocks, 256>>>(att + (size_t)t * 128, bias + (size_t)t * 128,
                                   (t == 4) ? out : nullptr);
    }
}